// round 15
// baseline (speedup 1.0000x reference)
#include <cuda_runtime.h>
#include <math.h>

#define LAY 2
#define BB 64
#define HH 1024
#define TT 512
#define ON 1024
#define NBLK 128
#define NTHR 512
#define CH 64
#define PS 68
#define ATS (64*PS)
#define BTS (32*PS)
#define STG (2*ATS + 2*BTS)
#define GSZ (64*33)
#define SMEMF (3*STG + 2*GSZ)
#define BH (BB*HH)

__device__ __align__(256) float g_h[2][LAY*BH];
__device__ __align__(256) float g_x0[BH];
__device__ unsigned g_gen, g_cnt;

// ---- XLA-replica nonlinearities (validated R14) ----
__device__ __forceinline__ float tanh_xla(float x){
  float xc = fminf(fmaxf(x, -7.90531110763549805f), 7.90531110763549805f);
  float x2 = __fmul_rn(xc, xc);
  float p = -2.76076847742355e-16f;
  p = __fmaf_rn(x2, p,  2.00018790482477e-13f);
  p = __fmaf_rn(x2, p, -8.60467152213735e-11f);
  p = __fmaf_rn(x2, p,  5.12229709037114e-08f);
  p = __fmaf_rn(x2, p,  1.48572235717979e-05f);
  p = __fmaf_rn(x2, p,  6.37261928875436e-04f);
  p = __fmaf_rn(x2, p,  4.89352455891786e-03f);
  float num = __fmul_rn(xc, p);
  float q =  1.19825839466702e-06f;
  q = __fmaf_rn(x2, q, 1.18534705686654e-04f);
  q = __fmaf_rn(x2, q, 2.26843463243900e-03f);
  q = __fmaf_rn(x2, q, 4.89352518554385e-03f);
  float r = __fdiv_rn(num, q);
  return (fabsf(x) < 0.0004f) ? x : r;
}
__device__ __forceinline__ float sigm_xla(float x){
  return __fadd_rn(0.5f, __fmul_rn(0.5f, tanh_xla(__fmul_rn(0.5f, x))));
}

// ---- cp.async (.cg: L2-coherent cross-CTA reads) ----
__device__ __forceinline__ void cp16(float* d, const float* s){
  unsigned a=(unsigned)__cvta_generic_to_shared(d);
  asm volatile("cp.async.cg.shared.global [%0],[%1],16;\n"::"r"(a),"l"(s));
}
__device__ __forceinline__ void commit(){ asm volatile("cp.async.commit_group;\n":::"memory"); }
__device__ __forceinline__ void wait1(){ asm volatile("cp.async.wait_group 1;\n":::"memory"); }

// A tile: 64 rows x 64 floats (2 float4 per thread)
__device__ __forceinline__ void cpA(float* dst, const float* src, int tid){
#pragma unroll
  for(int i=0;i<2;i++){
    int u = tid + i*NTHR, r = u>>4, c = u&15;
    cp16(dst + r*PS + (c<<2), src + r*HH + (c<<2));
  }
}
// gate-weight tile: 32 rows (gate*8 + j), 1 float4 per thread
__device__ __forceinline__ void cpBg(float* dst, const float* W, int jb, int koff, int tid){
  int r = tid>>4, c = tid&15;
  size_t gr = (size_t)((r>>3)*HH + jb + (r&7));
  cp16(dst + r*PS + (c<<2), W + gr*HH + koff + (c<<2));
}
// fc-weight tile: 8 rows jb..jb+7 (threads 0..127)
__device__ __forceinline__ void cpBf(float* dst, const float* W, int jb, int koff, int tid){
  if(tid < 128){
    int r = tid>>4, c = tid&15;
    cp16(dst + r*PS + (c<<2), W + (size_t)(jb+r)*HH + koff + (c<<2));
  }
}

// one CH=64 chunk; 2-way split accumulation (pairwise, matches R14)
__device__ __forceinline__ void ffma_g(const float* As, const float* Bs,
                                       int v8, int n, float* acc){
  float c0[8], c1[8];
#pragma unroll
  for(int i=0;i<8;i++){ c0[i]=0.f; c1[i]=0.f; }
#pragma unroll
  for(int k4=0;k4<16;k4++){
    float* cc = (k4&1) ? c1 : c0;
    const float4 bv = *(const float4*)(Bs + n*PS + (k4<<2));
#pragma unroll
    for(int i=0;i<8;i++){
      const float4 av = *(const float4*)(As + (v8+i)*PS + (k4<<2));
      cc[i] = __fmaf_rn(av.x, bv.x, cc[i]);
      cc[i] = __fmaf_rn(av.y, bv.y, cc[i]);
      cc[i] = __fmaf_rn(av.z, bv.z, cc[i]);
      cc[i] = __fmaf_rn(av.w, bv.w, cc[i]);
    }
  }
#pragma unroll
  for(int i=0;i<8;i++) acc[i] = __fadd_rn(acc[i], __fadd_rn(c0[i], c1[i]));
}
__device__ __forceinline__ void ffma_f(const float* As, const float* Bs,
                                       int b, int j, float* acc){
  float d0=0.f, d1=0.f;
#pragma unroll
  for(int k4=0;k4<16;k4++){
    const float4 bv = *(const float4*)(Bs + j*PS + (k4<<2));
    const float4 av = *(const float4*)(As + b*PS + (k4<<2));
    float s;
    s = __fmaf_rn(av.x, bv.x, (k4&1)?d1:d0);
    s = __fmaf_rn(av.y, bv.y, s);
    s = __fmaf_rn(av.z, bv.z, s);
    s = __fmaf_rn(av.w, bv.w, s);
    if(k4&1) d1 = s; else d0 = s;
  }
  *acc = __fadd_rn(*acc, __fadd_rn(d0, d1));
}

__device__ __forceinline__ void grid_sync(unsigned* lgen){
  __syncthreads();
  if(threadIdx.x==0){
    unsigned tgt = ++(*lgen);
    __threadfence();
    if(atomicAdd(&g_cnt,1u)==NBLK-1u){
      atomicExch(&g_cnt,0u);
      __threadfence();
      atomicExch(&g_gen,tgt);
    } else {
      while(*(volatile unsigned*)&g_gen < tgt) __nanosleep(32);
      __threadfence();
    }
  }
  __syncthreads();
}

__global__ void lstm_init(const float* __restrict__ hidden, const float* __restrict__ iv){
  int n = blockIdx.x*blockDim.x + threadIdx.x;
  if(n < LAY*BH) g_h[0][n] = hidden[n];
  if(n < BH) g_x0[n] = iv[n & (HH-1)];
  if(n==0){ g_gen=0u; g_cnt=0u; }
}

__global__ void __launch_bounds__(NTHR,1) lstm_main(
  const float* __restrict__ cell, const float* __restrict__ W_ih, const float* __restrict__ W_hh,
  const float* __restrict__ b_ih, const float* __restrict__ b_hh,
  const float* __restrict__ fc_w, const float* __restrict__ fc_b, float* __restrict__ out)
{
  extern __shared__ float sm[];
  // stage s block: [Ax | Ah | Bx | Bh]
  float* St[3]; St[0]=sm; St[1]=sm+STG; St[2]=sm+2*STG;
  float* G1 = sm + 3*STG;
  float* G2 = G1 + GSZ;

  const int tid=threadIdx.x, blk=blockIdx.x;
  const int lane=tid&31, wid=tid>>5;
  const int wg = wid>>3;          // 0: x-part (S1), 1: h-part (S2)
  const int v8 = (wid&7)*8;       // batches v8..v8+7
  const int cb = tid>>3;          // combine/fc batch
  const int cj = tid&7;           // combine/fc j
  const int jb = blk*8;

  // per-thread state: 1 combine slot
  float cr0 = cell[0*BH + cb*HH + jb + cj];
  float cr1 = cell[1*BH + cb*HH + jb + cj];
  float biv[2][4], bhv[2][4];
#pragma unroll
  for(int l=0;l<2;l++)
#pragma unroll
    for(int g=0;g<4;g++){
      biv[l][g] = b_ih[l*4*HH + g*HH + jb + cj];
      bhv[l][g] = b_hh[l*4*HH + g*HH + jb + cj];
    }
  const float fcb = fc_b[jb + cj];

  unsigned lgen=0;
#pragma unroll 1
  for(int t=0;t<TT;t++){
    const int rb=t&1, wb=rb^1;
    const float* xin = (t==0) ? g_x0 : g_h[rb]+BH;
#pragma unroll 1
    for(int l=0;l<LAY;l++){
      const float* xa = (l==0) ? xin : g_h[wb];
      const float* ha = g_h[rb]+l*BH;
      const float* Wi = W_ih + (size_t)l*4*HH*HH;
      const float* Wh = W_hh + (size_t)l*4*HH*HH;

      // prologue: stage chunks 0,1
#pragma unroll
      for(int c=0;c<2;c++){
        float* S = St[c];
        cpA(S,           xa + c*CH, tid);
        cpA(S+ATS,       ha + c*CH, tid);
        cpBg(S+2*ATS,     Wi, jb, c*CH, tid);
        cpBg(S+2*ATS+BTS, Wh, jb, c*CH, tid);
        commit();
      }
      float acc[8]={0,0,0,0,0,0,0,0};
#pragma unroll 1
      for(int c=0;c<16;c++){
        wait1(); __syncthreads();
        float* S = St[c%3];
        if(wg==0) ffma_g(S,     S+2*ATS,     v8, lane, acc);
        else      ffma_g(S+ATS, S+2*ATS+BTS, v8, lane, acc);
        int c2=c+2;
        if(c2<16){
          float* S2p = St[c2%3];
          cpA(S2p,           xa + c2*CH, tid);
          cpA(S2p+ATS,       ha + c2*CH, tid);
          cpBg(S2p+2*ATS,     Wi, jb, c2*CH, tid);
          cpBg(S2p+2*ATS+BTS, Wh, jb, c2*CH, tid);
        }
        commit();
      }
      // write partial sums
      float* Gp = wg ? G2 : G1;
#pragma unroll
      for(int i=0;i<8;i++) Gp[(v8+i)*33 + lane] = acc[i];
      __syncthreads();

      // combine: ((S1+S2)+bi)+bh, one slot per thread
      {
        const float* g1 = G1 + cb*33;
        const float* g2 = G2 + cb*33;
        float ig = __fadd_rn(__fadd_rn(__fadd_rn(g1[cj],    g2[cj]),    biv[l][0]), bhv[l][0]);
        float fg = __fadd_rn(__fadd_rn(__fadd_rn(g1[8+cj],  g2[8+cj]),  biv[l][1]), bhv[l][1]);
        float gg = __fadd_rn(__fadd_rn(__fadd_rn(g1[16+cj], g2[16+cj]), biv[l][2]), bhv[l][2]);
        float og = __fadd_rn(__fadd_rn(__fadd_rn(g1[24+cj], g2[24+cj]), biv[l][3]), bhv[l][3]);
        float cold = (l==0) ? cr0 : cr1;
        float cn = __fadd_rn(__fmul_rn(sigm_xla(fg), cold),
                             __fmul_rn(sigm_xla(ig), tanh_xla(gg)));
        if(l==0) cr0 = cn; else cr1 = cn;
        g_h[wb][l*BH + cb*HH + jb + cj] = __fmul_rn(sigm_xla(og), tanh_xla(cn));
      }
      grid_sync(&lgen);
    }

    // fc: out[b, t, jb+j] = h1 . fc_w[jb+j] + fc_b
    {
      const float* h1 = g_h[wb]+BH;
#pragma unroll
      for(int c=0;c<2;c++){
        float* S = St[c];
        cpA(S, h1 + c*CH, tid);
        cpBf(S+2*ATS, fc_w, jb, c*CH, tid);
        commit();
      }
      float fa = 0.f;
#pragma unroll 1
      for(int c=0;c<16;c++){
        wait1(); __syncthreads();
        float* S = St[c%3];
        ffma_f(S, S+2*ATS, cb, cj, &fa);
        int c2=c+2;
        if(c2<16){
          float* S2p = St[c2%3];
          cpA(S2p, h1 + c2*CH, tid);
          cpBf(S2p+2*ATS, fc_w, jb, c2*CH, tid);
        }
        commit();
      }
      out[(size_t)cb*TT*ON + (size_t)t*ON + jb + cj] = __fadd_rn(fa, fcb);
      __syncthreads();   // stage buffers safe before next step's prologue
    }
  }
}

extern "C" void kernel_launch(void* const* d_in, const int* in_sizes, int n_in,
                              void* d_out, int out_size){
  const float* hidden=(const float*)d_in[0];
  const float* cell  =(const float*)d_in[1];
  const float* W_ih  =(const float*)d_in[2];
  const float* W_hh  =(const float*)d_in[3];
  const float* b_ih  =(const float*)d_in[4];
  const float* b_hh  =(const float*)d_in[5];
  const float* fc_w  =(const float*)d_in[6];
  const float* fc_b  =(const float*)d_in[7];
  const float* iv    =(const float*)d_in[8];
  float* out=(float*)d_out;
  cudaFuncSetAttribute(lstm_main, cudaFuncAttributeMaxDynamicSharedMemorySize, SMEMF*4);
  lstm_init<<<512,256>>>(hidden, iv);
  lstm_main<<<NBLK,NTHR,SMEMF*4>>>(cell,W_ih,W_hh,b_ih,b_hh,fc_w,fc_b,out);
}

// round 16
// speedup vs baseline: 1.2248x; 1.2248x over previous
#include <cuda_runtime.h>
#include <math.h>

#define LAY 2
#define BB 64
#define HH 1024
#define TT 512
#define ON 1024
#define NBLK 128
#define NTHR 512
#define CH 128
#define ASZ (64*CH)
#define BSZ (32*CH)
#define STG (ASZ+BSZ)
#define GSZ (64*33)
#define SMEMF (3*STG + GSZ)
#define BH (BB*HH)

__device__ __align__(256) float g_h[2][LAY*BH];
__device__ __align__(256) float g_x0[BH];
__device__ unsigned g_gen, g_cnt;

// ---- XLA-replica nonlinearities (validated R14) ----
__device__ __forceinline__ float tanh_xla(float x){
  float xc = fminf(fmaxf(x, -7.90531110763549805f), 7.90531110763549805f);
  float x2 = __fmul_rn(xc, xc);
  float p = -2.76076847742355e-16f;
  p = __fmaf_rn(x2, p,  2.00018790482477e-13f);
  p = __fmaf_rn(x2, p, -8.60467152213735e-11f);
  p = __fmaf_rn(x2, p,  5.12229709037114e-08f);
  p = __fmaf_rn(x2, p,  1.48572235717979e-05f);
  p = __fmaf_rn(x2, p,  6.37261928875436e-04f);
  p = __fmaf_rn(x2, p,  4.89352455891786e-03f);
  float num = __fmul_rn(xc, p);
  float q =  1.19825839466702e-06f;
  q = __fmaf_rn(x2, q, 1.18534705686654e-04f);
  q = __fmaf_rn(x2, q, 2.26843463243900e-03f);
  q = __fmaf_rn(x2, q, 4.89352518554385e-03f);
  float r = __fdiv_rn(num, q);
  return (fabsf(x) < 0.0004f) ? x : r;
}
__device__ __forceinline__ float sigm_xla(float x){
  return __fadd_rn(0.5f, __fmul_rn(0.5f, tanh_xla(__fmul_rn(0.5f, x))));
}

// ---- cp.async (.cg: L2-coherent cross-CTA reads) ----
__device__ __forceinline__ void cp16(float* d, const float* s){
  unsigned a=(unsigned)__cvta_generic_to_shared(d);
  asm volatile("cp.async.cg.shared.global [%0],[%1],16;\n"::"r"(a),"l"(s));
}
__device__ __forceinline__ void commit(){ asm volatile("cp.async.commit_group;\n":::"memory"); }
__device__ __forceinline__ void wait1(){ asm volatile("cp.async.wait_group 1;\n":::"memory"); }

// A tile: 64 rows x 128 floats (XOR swizzle, R14 layout), 4 float4/thread
__device__ __forceinline__ void cpA(float* dst, const float* src, int tid){
#pragma unroll
  for(int i=0;i<4;i++){
    int u = tid + i*NTHR, r = u>>5, c = u&31;
    cp16(dst + r*CH + ((c ^ (r&31))<<2), src + r*HH + (c<<2));
  }
}
// gate-weight tile: 32 rows (gate*8+j), 2 float4/thread
__device__ __forceinline__ void cpBg(float* dst, const float* W, int jb, int koff, int tid){
#pragma unroll
  for(int i=0;i<2;i++){
    int u = tid + i*NTHR, r = u>>5, c = u&31;
    size_t gr = (size_t)((r>>3)*HH + jb + (r&7));
    cp16(dst + r*CH + ((c ^ r)<<2), W + gr*HH + koff + (c<<2));
  }
}
// fc-weight tile: 8 rows jb..jb+7 (threads 0..255)
__device__ __forceinline__ void cpBf(float* dst, const float* W, int jb, int koff, int tid){
  if(tid < 256){
    int r = tid>>5, c = tid&31;
    cp16(dst + r*CH + ((c ^ r)<<2), W + (size_t)(jb+r)*HH + koff + (c<<2));
  }
}

// one CH=128 chunk; warp tile = 4 batches x 32 gate-rows; 2-way split accumulation
__device__ __forceinline__ void ffma_g(const float* As, const float* Bs,
                                       int v4, int n, float* acc){
  float c0[4], c1[4];
#pragma unroll
  for(int i=0;i<4;i++){ c0[i]=0.f; c1[i]=0.f; }
#pragma unroll
  for(int k4=0;k4<32;k4++){
    float* cc = (k4&1) ? c1 : c0;
    const float4 bv = *(const float4*)(Bs + n*CH + ((k4 ^ n)<<2));
#pragma unroll
    for(int i=0;i<4;i++){
      int b = v4 + i;
      const float4 av = *(const float4*)(As + b*CH + ((k4 ^ (b&31))<<2));
      cc[i] = __fmaf_rn(av.x, bv.x, cc[i]);
      cc[i] = __fmaf_rn(av.y, bv.y, cc[i]);
      cc[i] = __fmaf_rn(av.z, bv.z, cc[i]);
      cc[i] = __fmaf_rn(av.w, bv.w, cc[i]);
    }
  }
#pragma unroll
  for(int i=0;i<4;i++) acc[i] = __fadd_rn(acc[i], __fadd_rn(c0[i], c1[i]));
}
// fc chunk: 1 output (batch b, row j) per thread
__device__ __forceinline__ void ffma_f(const float* As, const float* Bs,
                                       int b, int j, float* acc){
  float d0=0.f, d1=0.f;
#pragma unroll
  for(int k4=0;k4<32;k4++){
    const float4 bv = *(const float4*)(Bs + j*CH + ((k4 ^ j)<<2));
    const float4 av = *(const float4*)(As + b*CH + ((k4 ^ (b&31))<<2));
    float s = (k4&1) ? d1 : d0;
    s = __fmaf_rn(av.x, bv.x, s);
    s = __fmaf_rn(av.y, bv.y, s);
    s = __fmaf_rn(av.z, bv.z, s);
    s = __fmaf_rn(av.w, bv.w, s);
    if(k4&1) d1 = s; else d0 = s;
  }
  *acc = __fadd_rn(*acc, __fadd_rn(d0, d1));
}

__device__ __forceinline__ void grid_sync(unsigned* lgen){
  __syncthreads();
  if(threadIdx.x==0){
    unsigned tgt = ++(*lgen);
    __threadfence();
    if(atomicAdd(&g_cnt,1u)==NBLK-1u){
      atomicExch(&g_cnt,0u);
      __threadfence();
      atomicExch(&g_gen,tgt);
    } else {
      while(*(volatile unsigned*)&g_gen < tgt) __nanosleep(32);
      __threadfence();
    }
  }
  __syncthreads();
}

__global__ void lstm_init(const float* __restrict__ hidden, const float* __restrict__ iv){
  int n = blockIdx.x*blockDim.x + threadIdx.x;
  if(n < LAY*BH) g_h[0][n] = hidden[n];
  if(n < BH) g_x0[n] = iv[n & (HH-1)];
  if(n==0){ g_gen=0u; g_cnt=0u; }
}

__global__ void __launch_bounds__(NTHR,1) lstm_main(
  const float* __restrict__ cell, const float* __restrict__ W_ih, const float* __restrict__ W_hh,
  const float* __restrict__ b_ih, const float* __restrict__ b_hh,
  const float* __restrict__ fc_w, const float* __restrict__ fc_b, float* __restrict__ out)
{
  extern __shared__ float sm[];
  float* St[3]; St[0]=sm; St[1]=sm+STG; St[2]=sm+2*STG;   // stage: [A | B]
  float* G = sm + 3*STG;

  const int tid=threadIdx.x, blk=blockIdx.x;
  const int lane=tid&31, wid=tid>>5;
  const int v4 = wid*4;           // 16 warps x 4 batches
  const int cb = tid>>3;          // combine/fc batch (0..63)
  const int cj = tid&7;           // combine/fc j
  const int jb = blk*8;

  float cr0 = cell[0*BH + cb*HH + jb + cj];
  float cr1 = cell[1*BH + cb*HH + jb + cj];
  float biv[2][4], bhv[2][4];
#pragma unroll
  for(int l=0;l<2;l++)
#pragma unroll
    for(int g=0;g<4;g++){
      biv[l][g] = b_ih[l*4*HH + g*HH + jb + cj];
      bhv[l][g] = b_hh[l*4*HH + g*HH + jb + cj];
    }
  const float fcb = fc_b[jb + cj];

  unsigned lgen=0;
#pragma unroll 1
  for(int t=0;t<TT;t++){
    const int rb=t&1, wb=rb^1;
    const float* xin = (t==0) ? g_x0 : g_h[rb]+BH;
#pragma unroll 1
    for(int l=0;l<LAY;l++){
      const float* xa = (l==0) ? xin : g_h[wb];
      const float* ha = g_h[rb]+l*BH;
      const float* Wi = W_ih + (size_t)l*4*HH*HH;
      const float* Wh = W_hh + (size_t)l*4*HH*HH;

      // prologue: chunks 0,1 -> St[0],St[1]
#pragma unroll
      for(int c=0;c<2;c++){
        cpA(St[c], xa + c*CH, tid);
        cpBg(St[c]+ASZ, Wi, jb, c*CH, tid);
        commit();
      }
      float acc[4]={0,0,0,0}, sx[4];
#pragma unroll 1
      for(int c=0;c<16;c++){
        wait1(); __syncthreads();
        float* S = St[c%3];
        ffma_g(S, S+ASZ, v4, lane, acc);
        if(c==7){
#pragma unroll
          for(int i=0;i<4;i++){ sx[i]=acc[i]; acc[i]=0.f; }  // S1 = x@W_ih^T
        }
        int c2=c+2;
        if(c2<16){
          float* S2 = St[c2%3];
          int off=(c2&7)*CH;
          const float* A2 = (c2<8) ? xa : ha;
          const float* W2 = (c2<8) ? Wi : Wh;
          cpA(S2, A2+off, tid); cpBg(S2+ASZ, W2, jb, off, tid);
        }
        commit();
      }
      // G = S1 + S2 (JAX order)
#pragma unroll
      for(int i=0;i<4;i++) G[(v4+i)*33 + lane] = __fadd_rn(sx[i], acc[i]);
      __syncthreads();

      {
        const float* Gr = G + cb*33;
        float ig = __fadd_rn(__fadd_rn(Gr[cj],    biv[l][0]), bhv[l][0]);
        float fg = __fadd_rn(__fadd_rn(Gr[8+cj],  biv[l][1]), bhv[l][1]);
        float gg = __fadd_rn(__fadd_rn(Gr[16+cj], biv[l][2]), bhv[l][2]);
        float og = __fadd_rn(__fadd_rn(Gr[24+cj], biv[l][3]), bhv[l][3]);
        float cold = (l==0) ? cr0 : cr1;
        float cn = __fadd_rn(__fmul_rn(sigm_xla(fg), cold),
                             __fmul_rn(sigm_xla(ig), tanh_xla(gg)));
        if(l==0) cr0 = cn; else cr1 = cn;
        g_h[wb][l*BH + cb*HH + jb + cj] = __fmul_rn(sigm_xla(og), tanh_xla(cn));
      }
      grid_sync(&lgen);
    }

    // fc: out[b, t, jb+j] = h1 . fc_w[jb+j] + fc_b
    {
      const float* h1 = g_h[wb]+BH;
#pragma unroll
      for(int c=0;c<2;c++){
        cpA(St[c], h1 + c*CH, tid);
        cpBf(St[c]+ASZ, fc_w, jb, c*CH, tid);
        commit();
      }
      float fa = 0.f;
#pragma unroll 1
      for(int c=0;c<8;c++){
        wait1(); __syncthreads();
        float* S = St[c%3];
        ffma_f(S, S+ASZ, cb, cj, &fa);
        int c2=c+2;
        if(c2<8){
          cpA(St[c2%3], h1 + c2*CH, tid);
          cpBf(St[c2%3]+ASZ, fc_w, jb, c2*CH, tid);
        }
        commit();
      }
      out[(size_t)cb*TT*ON + (size_t)t*ON + jb + cj] = __fadd_rn(fa, fcb);
      __syncthreads();   // all fc reads done before next step's prologue rewrites St[0..1]
    }
  }
}

extern "C" void kernel_launch(void* const* d_in, const int* in_sizes, int n_in,
                              void* d_out, int out_size){
  const float* hidden=(const float*)d_in[0];
  const float* cell  =(const float*)d_in[1];
  const float* W_ih  =(const float*)d_in[2];
  const float* W_hh  =(const float*)d_in[3];
  const float* b_ih  =(const float*)d_in[4];
  const float* b_hh  =(const float*)d_in[5];
  const float* fc_w  =(const float*)d_in[6];
  const float* fc_b  =(const float*)d_in[7];
  const float* iv    =(const float*)d_in[8];
  float* out=(float*)d_out;
  cudaFuncSetAttribute(lstm_main, cudaFuncAttributeMaxDynamicSharedMemorySize, SMEMF*4);
  lstm_init<<<512,256>>>(hidden, iv);
  lstm_main<<<NBLK,NTHR,SMEMF*4>>>(cell,W_ih,W_hh,b_ih,b_hh,fc_w,fc_b,out);
}